// round 13
// baseline (speedup 1.0000x reference)
#include <cuda_runtime.h>
#include <cuda_fp16.h>
#include <math.h>

#define DIMS 1024
#define KSZ  128
#define SEQ  2048
#define BATCH 8
#define M_TOTAL (BATCH*SEQ)     // 16384
#define OUTD (DIMS + KSZ)       // 1152

// scratch (allocation-free rule: __device__ globals)
__device__ __half g_xh[M_TOTAL * DIMS];                 // X fp16
__device__ __half g_wth[2 * KSZ * DIMS];                // [n=256][k=1024] W^T fp16
__device__ __half g_keys_h[M_TOTAL * KSZ];              // keys fp16 [tok][dim]
__device__ __half g_valsT_h[(size_t)BATCH * KSZ * SEQ]; // vals^T fp16 [b][dim][tok]

// ---------------------------------------------------------------------------
// helpers
// ---------------------------------------------------------------------------
__device__ __forceinline__ void cp16a(unsigned daddr, const void* src) {
    asm volatile("cp.async.cg.shared.global [%0], [%1], 16;" :: "r"(daddr), "l"(src));
}
#define CP_COMMIT() asm volatile("cp.async.commit_group;")
#define CP_WAIT(n)  asm volatile("cp.async.wait_group %0;" :: "n"(n))

__device__ __forceinline__ void mma_f16(float* c,
        unsigned a0, unsigned a1, unsigned a2, unsigned a3,
        unsigned b0, unsigned b1) {
    asm volatile(
        "mma.sync.aligned.m16n8k16.row.col.f32.f16.f16.f32 "
        "{%0,%1,%2,%3}, {%4,%5,%6,%7}, {%8,%9}, {%0,%1,%2,%3};"
        : "+f"(c[0]), "+f"(c[1]), "+f"(c[2]), "+f"(c[3])
        : "r"(a0), "r"(a1), "r"(a2), "r"(a3), "r"(b0), "r"(b1));
}

__device__ __forceinline__ void ldmat_x4(unsigned& r0, unsigned& r1,
                                         unsigned& r2, unsigned& r3, unsigned saddr) {
    asm volatile("ldmatrix.sync.aligned.m8n8.x4.shared.b16 {%0,%1,%2,%3}, [%4];"
        : "=r"(r0), "=r"(r1), "=r"(r2), "=r"(r3) : "r"(saddr));
}

__device__ __forceinline__ unsigned packh2(float lo, float hi) {
    __half2 h = __floats2half2_rn(lo, hi);
    return *(unsigned*)&h;
}

#define LDM_A_ROW(lane) ((((lane) >> 3) & 1) * 8 + ((lane) & 7))
#define LDM_A_K(lane)   ((((lane) >> 4) & 1) * 8)
#define LDM_B_ROW(lane) ((((lane) >> 4) & 1) * 8 + ((lane) & 7))
#define LDM_B_K(lane)   ((((lane) >> 3) & 1) * 8)

// ---------------------------------------------------------------------------
// Kernel P: fused prep. Blocks [0,8192): X -> g_xh fp16 (2 rows/block).
// Blocks [8192, 8192+64): W -> W^T fp16 via smem tile transpose (coalesced).
// ---------------------------------------------------------------------------
#define XBLKS 8192
__global__ __launch_bounds__(256) void prep_kernel(
        const float* __restrict__ X,
        const float* __restrict__ Wk, const float* __restrict__ Wv) {
    __shared__ float wt[128][33];
    const int tid = threadIdx.x;
    if (blockIdx.x < XBLKS) {
        const size_t row = (size_t)blockIdx.x * 2 + (tid >> 7);
        const int e0 = (tid & 127) * 8;
        const float* src = X + row * DIMS + e0;
        float4 v0 = *(const float4*)(src);
        float4 v1 = *(const float4*)(src + 4);
        uint4 h;
        h.x = packh2(v0.x, v0.y); h.y = packh2(v0.z, v0.w);
        h.z = packh2(v1.x, v1.y); h.w = packh2(v1.z, v1.w);
        *(uint4*)(g_xh + row * DIMS + e0) = h;
    } else {
        const int wb = blockIdx.x - XBLKS;   // 0..63
        const int mat = wb >> 5, tw = wb & 31;
        const int k0 = (tw >> 2) * 128, n0 = (tw & 3) * 32;
        const float* W = mat ? Wv : Wk;
        #pragma unroll
        for (int i = 0; i < 16; i++) {
            int idx = tid + i * 256;
            int kk = idx >> 5, nn = idx & 31;
            wt[kk][nn] = W[(size_t)(k0 + kk) * KSZ + n0 + nn];
        }
        __syncthreads();
        #pragma unroll
        for (int i = 0; i < 16; i++) {
            int idx = tid + i * 256;
            int nn = idx >> 7, kk = idx & 127;
            g_wth[(size_t)(mat * KSZ + n0 + nn) * DIMS + k0 + kk] =
                __float2half_rn(wt[kk][nn]);
        }
    }
}

// ---------------------------------------------------------------------------
// Kernel G: fused KV projection GEMM (lean).
// BM=128, BN=256, BK=64, 512 threads (16 warps 4m x 4n, warp tile 32x64).
// n 0..127 -> keys [tok][dim]; n 128..255 -> vals transposed [b][dim][tok].
// ---------------------------------------------------------------------------
#define GBK 64
#define ALD 72
#define BLD 72
#define GA_H (128 * ALD)                          // 9216
#define GB_H (256 * BLD)                          // 18432
#define GB_OFF (GA_H * 2)
#define GBUF_BYTES ((GA_H + GB_H) * 2)            // 55296
#define GEMM_SMEM_BYTES (2 * GBUF_BYTES)          // 110592

__global__ __launch_bounds__(512, 1) void kv_gemm_f16(
        const float* __restrict__ bk, const float* __restrict__ bv) {
    extern __shared__ char smc[];
    const unsigned sbase = (unsigned)__cvta_generic_to_shared(smc);
    const int tid = threadIdx.x, lane = tid & 31, wid = tid >> 5;
    const int g = lane >> 2, t = lane & 3;
    const int wm = wid & 3, wn = wid >> 2;        // 4 x 4 warps
    const int m0 = blockIdx.x * 128;

    const int raA = LDM_A_ROW(lane), kaA = LDM_A_K(lane);
    const int rbB = LDM_B_ROW(lane), kbB = LDM_B_K(lane);

    #define G_LOAD(bb, k0) do {                                               \
        unsigned ab = sbase + (bb) * GBUF_BYTES;                              \
        _Pragma("unroll")                                                     \
        for (int i = 0; i < 2; i++) {                                         \
            int idx = tid + i * 512;                                          \
            int row = idx >> 3, ch = idx & 7;                                 \
            cp16a(ab + (row * ALD + ch * 8) * 2,                              \
                  g_xh + (size_t)(m0 + row) * DIMS + (k0) + ch * 8);          \
        }                                                                     \
        _Pragma("unroll")                                                     \
        for (int i = 0; i < 4; i++) {                                         \
            int idx = tid + i * 512;                                          \
            int row = idx >> 3, ch = idx & 7;                                 \
            cp16a(ab + GB_OFF + (row * BLD + ch * 8) * 2,                     \
                  g_wth + (size_t)row * DIMS + (k0) + ch * 8);                \
        }                                                                     \
    } while (0)

    float acc[2][8][4];
    #pragma unroll
    for (int mt = 0; mt < 2; mt++)
        #pragma unroll
        for (int nt = 0; nt < 8; nt++)
            #pragma unroll
            for (int i = 0; i < 4; i++) acc[mt][nt][i] = 0.f;

    G_LOAD(0, 0);
    CP_COMMIT();

    const int NK = DIMS / GBK;   // 16
    for (int kk0 = 0; kk0 < NK; kk0++) {
        if (kk0 + 1 < NK) {
            G_LOAD((kk0 + 1) & 1, (kk0 + 1) * GBK);
            CP_COMMIT();
            CP_WAIT(1);
        } else {
            CP_WAIT(0);
        }
        __syncthreads();

        const unsigned ab = sbase + (kk0 & 1) * GBUF_BYTES;
        const unsigned aW = ab + ((wm * 32 + raA) * ALD + kaA) * 2;
        const unsigned bW = ab + GB_OFF + ((wn * 64 + rbB) * BLD + kbB) * 2;
        #pragma unroll
        for (int ks = 0; ks < 4; ks++) {
            const int kk = ks * 16;
            unsigned a[2][4];
            #pragma unroll
            for (int mt = 0; mt < 2; mt++)
                ldmat_x4(a[mt][0], a[mt][1], a[mt][2], a[mt][3],
                         aW + (mt * 16 * ALD + kk) * 2);
            #pragma unroll
            for (int ntp = 0; ntp < 4; ntp++) {
                unsigned b0a, b1a, b0b, b1b;
                ldmat_x4(b0a, b1a, b0b, b1b, bW + (ntp * 16 * BLD + kk) * 2);
                #pragma unroll
                for (int mt = 0; mt < 2; mt++) {
                    mma_f16(acc[mt][2 * ntp],
                            a[mt][0], a[mt][1], a[mt][2], a[mt][3], b0a, b1a);
                    mma_f16(acc[mt][2 * ntp + 1],
                            a[mt][0], a[mt][1], a[mt][2], a[mt][3], b0b, b1b);
                }
            }
        }
        __syncthreads();
    }

    if (wn < 2) {
        // keys: fp16 [tok][dim]
        #pragma unroll
        for (int mt = 0; mt < 2; mt++) {
            int row = m0 + wm * 32 + mt * 16 + g;
            #pragma unroll
            for (int nt = 0; nt < 8; nt++) {
                int col = wn * 64 + nt * 8 + 2 * t;
                float b0 = bk[col], b1 = bk[col + 1];
                *(unsigned*)&g_keys_h[(size_t)row * KSZ + col] =
                    packh2(acc[mt][nt][0] + b0, acc[mt][nt][1] + b1);
                *(unsigned*)&g_keys_h[(size_t)(row + 8) * KSZ + col] =
                    packh2(acc[mt][nt][2] + b0, acc[mt][nt][3] + b1);
            }
        }
        __syncthreads();
    } else {
        // vals: transpose via smem -> fp16 [b][dim][tok]
        __half* Vst = (__half*)smc;   // [dim 128][tok 128+8]
        #pragma unroll
        for (int mt = 0; mt < 2; mt++) {
            int r = wm * 32 + mt * 16 + g;
            #pragma unroll
            for (int nt = 0; nt < 8; nt++) {
                int dcol = (wn - 2) * 64 + nt * 8 + 2 * t;
                float b0 = bv[dcol], b1 = bv[dcol + 1];
                Vst[(dcol    ) * 136 + r    ] = __float2half_rn(acc[mt][nt][0] + b0);
                Vst[(dcol + 1) * 136 + r    ] = __float2half_rn(acc[mt][nt][1] + b1);
                Vst[(dcol    ) * 136 + r + 8] = __float2half_rn(acc[mt][nt][2] + b0);
                Vst[(dcol + 1) * 136 + r + 8] = __float2half_rn(acc[mt][nt][3] + b1);
            }
        }
        __syncthreads();
    }
    {
        __half* Vst = (__half*)smc;
        const int bb = m0 >> 11;
        const int tloc = m0 & 2047;
        #pragma unroll
        for (int i = 0; i < 4; i++) {
            int idx = tid + i * 512;
            int col = idx >> 4, ch = idx & 15;
            uint4 v = *(uint4*)&Vst[col * 136 + ch * 8];
            *(uint4*)&g_valsT_h[((size_t)bb * KSZ + col) * SEQ + tloc + ch * 8] = v;
        }
    }
}

// ---------------------------------------------------------------------------
// Kernel A: causal flash attention, fp16 mma + ldmatrix, dual warp-group.
// ADJACENT pairing: qt = 2*pairIdx + grp, so the longest block (qt 30,31)
// keeps both warp-groups alive for its whole runtime (block time = max of
// the two groups; one wave of 128 blocks => total = slowest block).
// ---------------------------------------------------------------------------
#define AQ 64
#define AK 64
#define KLD 136
#define VLD 72
#define PLD 72
#define NQT (SEQ / AQ)               // 32
#define K_TILE_H (AK * KLD)          // 8704
#define VT_TILE_H (KSZ * VLD)        // 9216
#define GOFF_K0 0
#define GOFF_K1 (K_TILE_H)
#define GOFF_VT0 (2 * K_TILE_H)
#define GOFF_VT1 (2 * K_TILE_H + VT_TILE_H)
#define GOFF_P  (2 * K_TILE_H + 2 * VT_TILE_H)
#define GRP_H (GOFF_P + AQ * PLD)
#define ATTN_SMEM_BYTES (2 * GRP_H * 2)             // 161792

__global__ __launch_bounds__(256, 1) void attn_kernel(float* __restrict__ out) {
    extern __shared__ char smc[];
    const int tid = threadIdx.x, lane = tid & 31, wid = tid >> 5;
    const int g = lane >> 2, t = lane & 3;
    const int grp = wid >> 2, wg = wid & 3, gt = tid & 127;
    const int barid = grp + 1;
    #define GBAR() asm volatile("bar.sync %0, 128;" :: "r"(barid))

    char* gbase = smc + grp * GRP_H * 2;
    const unsigned sgb = (unsigned)__cvta_generic_to_shared(gbase);

    const int pairIdx = blockIdx.x;
    const int bq = blockIdx.y;
    const int qt = 2 * pairIdx + grp;        // adjacent pairing
    const int qbase = qt * AQ;
    const int nkt = qt + 1;
    const __half* keys = g_keys_h + (size_t)bq * SEQ * KSZ;
    const __half* valsT = g_valsT_h + (size_t)bq * KSZ * SEQ;
    const float scale = 0.08838834764831843f;   // 1/sqrt(128)

    const int raA = LDM_A_ROW(lane), kaA = LDM_A_K(lane);
    const int rbB = LDM_B_ROW(lane), kbB = LDM_B_K(lane);
    const int rw = wg * 16;

    #define LOAD_KV(buf, kbase) do {                                          \
        _Pragma("unroll")                                                     \
        for (int i = 0; i < 8; i++) {                                         \
            int idx = gt + i * 128;                                           \
            int row = idx >> 4, ch = idx & 15;                                \
            cp16a(sgb + ((buf ? GOFF_K1 : GOFF_K0) + row * KLD + ch * 8) * 2, \
                  keys + (size_t)((kbase) + row) * KSZ + ch * 8);             \
        }                                                                     \
        _Pragma("unroll")                                                     \
        for (int i = 0; i < 8; i++) {                                         \
            int idx = gt + i * 128;                                           \
            int row = idx >> 3, ch = idx & 7;                                 \
            cp16a(sgb + ((buf ? GOFF_VT1 : GOFF_VT0) + row * VLD + ch * 8) * 2, \
                  valsT + (size_t)row * SEQ + (kbase) + ch * 8);              \
        }                                                                     \
    } while (0)

    // stage Q through K0 region
    #pragma unroll
    for (int i = 0; i < 8; i++) {
        int idx = gt + i * 128;
        int row = idx >> 4, ch = idx & 15;
        cp16a(sgb + (row * KLD + ch * 8) * 2,
              keys + (size_t)(qbase + row) * KSZ + ch * 8);
    }
    CP_COMMIT();
    CP_WAIT(0);
    GBAR();

    // Q fragments via ldmatrix (a-type)
    unsigned qa[8][4];
    {
        const unsigned qW = sgb + ((rw + raA) * KLD + kaA) * 2;
        #pragma unroll
        for (int ks = 0; ks < 8; ks++)
            ldmat_x4(qa[ks][0], qa[ks][1], qa[ks][2], qa[ks][3], qW + ks * 32);
    }
    GBAR();

    LOAD_KV(0, 0);
    CP_COMMIT();

    float O[16][4];
    #pragma unroll
    for (int nt = 0; nt < 16; nt++)
        #pragma unroll
        for (int i = 0; i < 4; i++) O[nt][i] = 0.f;
    float mrow[2] = {-1e30f, -1e30f};
    float lrow[2] = {0.f, 0.f};

    for (int j = 0; j < nkt; j++) {
        if (j + 1 < nkt) {
            LOAD_KV((j + 1) & 1, (j + 1) * AK);
            CP_COMMIT();
            CP_WAIT(1);
        } else {
            CP_WAIT(0);
        }
        GBAR();

        const unsigned kW = sgb + ((j & 1) ? GOFF_K1 : GOFF_K0) * 2
                          + (rbB * KLD + kbB) * 2;
        const unsigned vW = sgb + ((j & 1) ? GOFF_VT1 : GOFF_VT0) * 2
                          + (rbB * VLD + kbB) * 2;
        unsigned* Ps32 = (unsigned*)(gbase + GOFF_P * 2);
        const int kbase = j * AK;

        // S = Q @ K^T : 16 rows x 64 keys
        float s[8][4];
        #pragma unroll
        for (int nt = 0; nt < 8; nt++)
            #pragma unroll
            for (int i = 0; i < 4; i++) s[nt][i] = 0.f;

        #pragma unroll
        for (int ks = 0; ks < 8; ks++) {
            #pragma unroll
            for (int ntp = 0; ntp < 4; ntp++) {
                unsigned b0a, b1a, b0b, b1b;
                ldmat_x4(b0a, b1a, b0b, b1b, kW + (ntp * 16 * KLD + ks * 16) * 2);
                mma_f16(s[2 * ntp],
                        qa[ks][0], qa[ks][1], qa[ks][2], qa[ks][3], b0a, b1a);
                mma_f16(s[2 * ntp + 1],
                        qa[ks][0], qa[ks][1], qa[ks][2], qa[ks][3], b0b, b1b);
            }
        }

        #pragma unroll
        for (int nt = 0; nt < 8; nt++)
            #pragma unroll
            for (int i = 0; i < 4; i++) s[nt][i] *= scale;

        // causal mask on diagonal tile only, exactly -100
        if (j == nkt - 1) {
            const int qg0 = qbase + rw + g;
            const int qg1 = qg0 + 8;
            #pragma unroll
            for (int nt = 0; nt < 8; nt++) {
                int kg = kbase + nt * 8 + 2 * t;
                if (kg     > qg0) s[nt][0] = -100.0f;
                if (kg + 1 > qg0) s[nt][1] = -100.0f;
                if (kg     > qg1) s[nt][2] = -100.0f;
                if (kg + 1 > qg1) s[nt][3] = -100.0f;
            }
        }

        // online softmax; O-rescale only when the running max changes
        #pragma unroll
        for (int h = 0; h < 2; h++) {
            float mx = -1e30f;
            #pragma unroll
            for (int nt = 0; nt < 8; nt++)
                mx = fmaxf(mx, fmaxf(s[nt][2 * h], s[nt][2 * h + 1]));
            mx = fmaxf(mx, __shfl_xor_sync(0xffffffffu, mx, 1));
            mx = fmaxf(mx, __shfl_xor_sync(0xffffffffu, mx, 2));
            if (mx > mrow[h]) {
                float alpha = __expf(mrow[h] - mx);
                mrow[h] = mx;
                lrow[h] *= alpha;
                #pragma unroll
                for (int nt = 0; nt < 16; nt++) {
                    O[nt][2 * h]     *= alpha;
                    O[nt][2 * h + 1] *= alpha;
                }
            }
            float m = mrow[h];
            float sum = 0.f;
            #pragma unroll
            for (int nt = 0; nt < 8; nt++) {
                float p0 = __expf(s[nt][2 * h] - m);
                float p1 = __expf(s[nt][2 * h + 1] - m);
                s[nt][2 * h] = p0; s[nt][2 * h + 1] = p1;
                sum += p0 + p1;
            }
            sum += __shfl_xor_sync(0xffffffffu, sum, 1);
            sum += __shfl_xor_sync(0xffffffffu, sum, 2);
            lrow[h] += sum;
        }

        // stage P as fp16 pairs in per-warp smem rows
        {
            #pragma unroll
            for (int nt = 0; nt < 8; nt++) {
                int col = nt * 8 + 2 * t;
                Ps32[((rw + g) * PLD + col) >> 1]     = packh2(s[nt][0], s[nt][1]);
                Ps32[((rw + g + 8) * PLD + col) >> 1] = packh2(s[nt][2], s[nt][3]);
            }
        }
        __syncwarp();

        // O += P @ V
        const unsigned pW = sgb + GOFF_P * 2 + ((rw + raA) * PLD + kaA) * 2;
        #pragma unroll
        for (int ks = 0; ks < 4; ks++) {
            unsigned pa0, pa1, pa2, pa3;
            ldmat_x4(pa0, pa1, pa2, pa3, pW + ks * 32);
            #pragma unroll
            for (int ntp = 0; ntp < 8; ntp++) {
                unsigned b0a, b1a, b0b, b1b;
                ldmat_x4(b0a, b1a, b0b, b1b, vW + (ntp * 16 * VLD + ks * 16) * 2);
                mma_f16(O[2 * ntp], pa0, pa1, pa2, pa3, b0a, b1a);
                mma_f16(O[2 * ntp + 1], pa0, pa1, pa2, pa3, b0b, b1b);
            }
        }
        GBAR();
    }

    // epilogue: normalize, write out[:, 1024:1152]
    {
        float inv0 = 1.0f / lrow[0];
        float inv1 = 1.0f / lrow[1];
        int qg0 = qbase + rw + g;
        size_t base0 = ((size_t)bq * SEQ + qg0) * OUTD + DIMS;
        size_t base1 = base0 + (size_t)8 * OUTD;
        #pragma unroll
        for (int nt = 0; nt < 16; nt++) {
            int c = nt * 8 + 2 * t;
            *(float2*)(out + base0 + c) = make_float2(O[nt][0] * inv0, O[nt][1] * inv0);
            *(float2*)(out + base1 + c) = make_float2(O[nt][2] * inv1, O[nt][3] * inv1);
        }
    }
}

// ---------------------------------------------------------------------------
// Kernel C: copy X into out[:,0:1024] (standalone; ~20us, DRAM-bound)
// ---------------------------------------------------------------------------
__global__ void copy_x_kernel(const float* __restrict__ X, float* __restrict__ out) {
    const size_t row = blockIdx.x;
    const int c = threadIdx.x * 4;
    float4 v = *(const float4*)(X + row * DIMS + c);
    *(float4*)(out + row * OUTD + c) = v;
}

// ---------------------------------------------------------------------------
extern "C" void kernel_launch(void* const* d_in, const int* in_sizes, int n_in,
                              void* d_out, int out_size) {
    const float* X  = (const float*)d_in[0];
    const float* Wk = (const float*)d_in[1];
    const float* bk = (const float*)d_in[2];
    const float* Wv = (const float*)d_in[3];
    const float* bv = (const float*)d_in[4];
    float* out = (float*)d_out;

    prep_kernel<<<XBLKS + 64, 256>>>(X, Wk, Wv);
    copy_x_kernel<<<M_TOTAL, 256>>>(X, out);

    cudaFuncSetAttribute(kv_gemm_f16, cudaFuncAttributeMaxDynamicSharedMemorySize,
                         GEMM_SMEM_BYTES);
    kv_gemm_f16<<<M_TOTAL / 128, 512, GEMM_SMEM_BYTES>>>(bk, bv);

    cudaFuncSetAttribute(attn_kernel, cudaFuncAttributeMaxDynamicSharedMemorySize,
                         ATTN_SMEM_BYTES);
    attn_kernel<<<dim3(NQT / 2, BATCH), 256, ATTN_SMEM_BYTES>>>(out);
}

// round 14
// speedup vs baseline: 1.3850x; 1.3850x over previous
#include <cuda_runtime.h>
#include <cuda_fp16.h>
#include <math.h>

#define DIMS 1024
#define KSZ  128
#define SEQ  2048
#define BATCH 8
#define M_TOTAL (BATCH*SEQ)     // 16384
#define OUTD (DIMS + KSZ)       // 1152

// scratch (allocation-free rule: __device__ globals)
__device__ __half g_xh[M_TOTAL * DIMS];                 // X fp16
__device__ __half g_wth[2 * KSZ * DIMS];                // [n=256][k=1024] W^T fp16
__device__ __half g_keys_h[M_TOTAL * KSZ];              // keys fp16 [tok][dim]
__device__ __half g_valsT_h[(size_t)BATCH * KSZ * SEQ]; // vals^T fp16 [b][dim][tok]

// ---------------------------------------------------------------------------
// helpers
// ---------------------------------------------------------------------------
__device__ __forceinline__ void cp16a(unsigned daddr, const void* src) {
    asm volatile("cp.async.cg.shared.global [%0], [%1], 16;" :: "r"(daddr), "l"(src));
}
#define CP_COMMIT() asm volatile("cp.async.commit_group;")
#define CP_WAIT(n)  asm volatile("cp.async.wait_group %0;" :: "n"(n))

__device__ __forceinline__ void mma_f16(float* c,
        unsigned a0, unsigned a1, unsigned a2, unsigned a3,
        unsigned b0, unsigned b1) {
    asm volatile(
        "mma.sync.aligned.m16n8k16.row.col.f32.f16.f16.f32 "
        "{%0,%1,%2,%3}, {%4,%5,%6,%7}, {%8,%9}, {%0,%1,%2,%3};"
        : "+f"(c[0]), "+f"(c[1]), "+f"(c[2]), "+f"(c[3])
        : "r"(a0), "r"(a1), "r"(a2), "r"(a3), "r"(b0), "r"(b1));
}

__device__ __forceinline__ void ldmat_x4(unsigned& r0, unsigned& r1,
                                         unsigned& r2, unsigned& r3, unsigned saddr) {
    asm volatile("ldmatrix.sync.aligned.m8n8.x4.shared.b16 {%0,%1,%2,%3}, [%4];"
        : "=r"(r0), "=r"(r1), "=r"(r2), "=r"(r3) : "r"(saddr));
}

__device__ __forceinline__ unsigned packh2(float lo, float hi) {
    __half2 h = __floats2half2_rn(lo, hi);
    return *(unsigned*)&h;
}

#define LDM_A_ROW(lane) ((((lane) >> 3) & 1) * 8 + ((lane) & 7))
#define LDM_A_K(lane)   ((((lane) >> 4) & 1) * 8)
#define LDM_B_ROW(lane) ((((lane) >> 4) & 1) * 8 + ((lane) & 7))
#define LDM_B_K(lane)   ((((lane) >> 3) & 1) * 8)

// ---------------------------------------------------------------------------
// Kernel P: fused prep. Blocks [0,8192): X -> out[:,0:1024] copy + g_xh fp16.
// Blocks [8192, 8192+64): W -> W^T fp16 via smem tile transpose (coalesced).
// ---------------------------------------------------------------------------
#define XBLKS 8192
__global__ __launch_bounds__(256) void prep_kernel(
        const float* __restrict__ X, float* __restrict__ out,
        const float* __restrict__ Wk, const float* __restrict__ Wv) {
    __shared__ float wt[128][33];
    const int tid = threadIdx.x;
    if (blockIdx.x < XBLKS) {
        const size_t row = (size_t)blockIdx.x * 2 + (tid >> 7);
        const int e0 = (tid & 127) * 8;
        const float* src = X + row * DIMS + e0;
        float4 v0 = *(const float4*)(src);
        float4 v1 = *(const float4*)(src + 4);
        *(float4*)(out + row * OUTD + e0) = v0;
        *(float4*)(out + row * OUTD + e0 + 4) = v1;
        uint4 h;
        h.x = packh2(v0.x, v0.y); h.y = packh2(v0.z, v0.w);
        h.z = packh2(v1.x, v1.y); h.w = packh2(v1.z, v1.w);
        *(uint4*)(g_xh + row * DIMS + e0) = h;
    } else {
        const int wb = blockIdx.x - XBLKS;   // 0..63
        const int mat = wb >> 5, tw = wb & 31;
        const int k0 = (tw >> 2) * 128, n0 = (tw & 3) * 32;
        const float* W = mat ? Wv : Wk;
        #pragma unroll
        for (int i = 0; i < 16; i++) {
            int idx = tid + i * 256;
            int kk = idx >> 5, nn = idx & 31;
            wt[kk][nn] = W[(size_t)(k0 + kk) * KSZ + n0 + nn];
        }
        __syncthreads();
        #pragma unroll
        for (int i = 0; i < 16; i++) {
            int idx = tid + i * 256;
            int nn = idx >> 7, kk = idx & 127;
            g_wth[(size_t)(mat * KSZ + n0 + nn) * DIMS + k0 + kk] =
                __float2half_rn(wt[kk][nn]);
        }
    }
}

// ---------------------------------------------------------------------------
// Kernel G: fused KV projection GEMM (lean).
// BM=128, BN=256, BK=64, 512 threads (16 warps 4m x 4n, warp tile 32x64).
// n 0..127 -> keys [tok][dim]; n 128..255 -> vals transposed [b][dim][tok].
// ---------------------------------------------------------------------------
#define GBK 64
#define ALD 72
#define BLD 72
#define GA_H (128 * ALD)                          // 9216
#define GB_H (256 * BLD)                          // 18432
#define GB_OFF (GA_H * 2)
#define GBUF_BYTES ((GA_H + GB_H) * 2)            // 55296
#define GEMM_SMEM_BYTES (2 * GBUF_BYTES)          // 110592

__global__ __launch_bounds__(512, 1) void kv_gemm_f16(
        const float* __restrict__ bk, const float* __restrict__ bv) {
    extern __shared__ char smc[];
    const unsigned sbase = (unsigned)__cvta_generic_to_shared(smc);
    const int tid = threadIdx.x, lane = tid & 31, wid = tid >> 5;
    const int g = lane >> 2, t = lane & 3;
    const int wm = wid & 3, wn = wid >> 2;        // 4 x 4 warps
    const int m0 = blockIdx.x * 128;

    const int raA = LDM_A_ROW(lane), kaA = LDM_A_K(lane);
    const int rbB = LDM_B_ROW(lane), kbB = LDM_B_K(lane);

    #define G_LOAD(bb, k0) do {                                               \
        unsigned ab = sbase + (bb) * GBUF_BYTES;                              \
        _Pragma("unroll")                                                     \
        for (int i = 0; i < 2; i++) {                                         \
            int idx = tid + i * 512;                                          \
            int row = idx >> 3, ch = idx & 7;                                 \
            cp16a(ab + (row * ALD + ch * 8) * 2,                              \
                  g_xh + (size_t)(m0 + row) * DIMS + (k0) + ch * 8);          \
        }                                                                     \
        _Pragma("unroll")                                                     \
        for (int i = 0; i < 4; i++) {                                         \
            int idx = tid + i * 512;                                          \
            int row = idx >> 3, ch = idx & 7;                                 \
            cp16a(ab + GB_OFF + (row * BLD + ch * 8) * 2,                     \
                  g_wth + (size_t)row * DIMS + (k0) + ch * 8);                \
        }                                                                     \
    } while (0)

    float acc[2][8][4];
    #pragma unroll
    for (int mt = 0; mt < 2; mt++)
        #pragma unroll
        for (int nt = 0; nt < 8; nt++)
            #pragma unroll
            for (int i = 0; i < 4; i++) acc[mt][nt][i] = 0.f;

    G_LOAD(0, 0);
    CP_COMMIT();

    const int NK = DIMS / GBK;   // 16
    for (int kk0 = 0; kk0 < NK; kk0++) {
        if (kk0 + 1 < NK) {
            G_LOAD((kk0 + 1) & 1, (kk0 + 1) * GBK);
            CP_COMMIT();
            CP_WAIT(1);
        } else {
            CP_WAIT(0);
        }
        __syncthreads();

        const unsigned ab = sbase + (kk0 & 1) * GBUF_BYTES;
        const unsigned aW = ab + ((wm * 32 + raA) * ALD + kaA) * 2;
        const unsigned bW = ab + GB_OFF + ((wn * 64 + rbB) * BLD + kbB) * 2;
        #pragma unroll
        for (int ks = 0; ks < 4; ks++) {
            const int kk = ks * 16;
            unsigned a[2][4];
            #pragma unroll
            for (int mt = 0; mt < 2; mt++)
                ldmat_x4(a[mt][0], a[mt][1], a[mt][2], a[mt][3],
                         aW + (mt * 16 * ALD + kk) * 2);
            #pragma unroll
            for (int ntp = 0; ntp < 4; ntp++) {
                unsigned b0a, b1a, b0b, b1b;
                ldmat_x4(b0a, b1a, b0b, b1b, bW + (ntp * 16 * BLD + kk) * 2);
                #pragma unroll
                for (int mt = 0; mt < 2; mt++) {
                    mma_f16(acc[mt][2 * ntp],
                            a[mt][0], a[mt][1], a[mt][2], a[mt][3], b0a, b1a);
                    mma_f16(acc[mt][2 * ntp + 1],
                            a[mt][0], a[mt][1], a[mt][2], a[mt][3], b0b, b1b);
                }
            }
        }
        __syncthreads();
    }

    if (wn < 2) {
        // keys: fp16 [tok][dim]
        #pragma unroll
        for (int mt = 0; mt < 2; mt++) {
            int row = m0 + wm * 32 + mt * 16 + g;
            #pragma unroll
            for (int nt = 0; nt < 8; nt++) {
                int col = wn * 64 + nt * 8 + 2 * t;
                float b0 = bk[col], b1 = bk[col + 1];
                *(unsigned*)&g_keys_h[(size_t)row * KSZ + col] =
                    packh2(acc[mt][nt][0] + b0, acc[mt][nt][1] + b1);
                *(unsigned*)&g_keys_h[(size_t)(row + 8) * KSZ + col] =
                    packh2(acc[mt][nt][2] + b0, acc[mt][nt][3] + b1);
            }
        }
        __syncthreads();
    } else {
        // vals: transpose via smem -> fp16 [b][dim][tok]
        __half* Vst = (__half*)smc;   // [dim 128][tok 128+8]
        #pragma unroll
        for (int mt = 0; mt < 2; mt++) {
            int r = wm * 32 + mt * 16 + g;
            #pragma unroll
            for (int nt = 0; nt < 8; nt++) {
                int dcol = (wn - 2) * 64 + nt * 8 + 2 * t;
                float b0 = bv[dcol], b1 = bv[dcol + 1];
                Vst[(dcol    ) * 136 + r    ] = __float2half_rn(acc[mt][nt][0] + b0);
                Vst[(dcol + 1) * 136 + r    ] = __float2half_rn(acc[mt][nt][1] + b1);
                Vst[(dcol    ) * 136 + r + 8] = __float2half_rn(acc[mt][nt][2] + b0);
                Vst[(dcol + 1) * 136 + r + 8] = __float2half_rn(acc[mt][nt][3] + b1);
            }
        }
        __syncthreads();
    }
    {
        __half* Vst = (__half*)smc;
        const int bb = m0 >> 11;
        const int tloc = m0 & 2047;
        #pragma unroll
        for (int i = 0; i < 4; i++) {
            int idx = tid + i * 512;
            int col = idx >> 4, ch = idx & 15;
            uint4 v = *(uint4*)&Vst[col * 136 + ch * 8];
            *(uint4*)&g_valsT_h[((size_t)bb * KSZ + col) * SEQ + tloc + ch * 8] = v;
        }
    }
}

// ---------------------------------------------------------------------------
// Kernel A: causal flash attention. (p, 31-p) pairing (balanced 33 tiles of
// total work per block — dual groups share SM throughput, so total work is
// what matters). P never touches smem: S accumulator fragments are repacked
// in registers directly into PV A-fragments (layouts match exactly).
// ---------------------------------------------------------------------------
#define AQ 64
#define AK 64
#define KLD 136
#define VLD 72
#define NQT (SEQ / AQ)               // 32
#define K_TILE_H (AK * KLD)          // 8704
#define VT_TILE_H (KSZ * VLD)        // 9216
#define GOFF_K0 0
#define GOFF_K1 (K_TILE_H)
#define GOFF_VT0 (2 * K_TILE_H)
#define GOFF_VT1 (2 * K_TILE_H + VT_TILE_H)
#define GRP_H (2 * K_TILE_H + 2 * VT_TILE_H)        // 35840
#define ATTN_SMEM_BYTES (2 * GRP_H * 2)             // 143360

__global__ __launch_bounds__(256, 1) void attn_kernel(float* __restrict__ out) {
    extern __shared__ char smc[];
    const int tid = threadIdx.x, lane = tid & 31, wid = tid >> 5;
    const int g = lane >> 2, t = lane & 3;
    const int grp = wid >> 2, wg = wid & 3, gt = tid & 127;
    const int barid = grp + 1;
    #define GBAR() asm volatile("bar.sync %0, 128;" :: "r"(barid))

    char* gbase = smc + grp * GRP_H * 2;
    const unsigned sgb = (unsigned)__cvta_generic_to_shared(gbase);

    const int pairIdx = blockIdx.x;
    const int bq = blockIdx.y;
    const int qt = grp ? (NQT - 1 - pairIdx) : pairIdx;   // balanced pairing
    const int qbase = qt * AQ;
    const int nkt = qt + 1;
    const __half* keys = g_keys_h + (size_t)bq * SEQ * KSZ;
    const __half* valsT = g_valsT_h + (size_t)bq * KSZ * SEQ;
    const float scale = 0.08838834764831843f;   // 1/sqrt(128)

    const int raA = LDM_A_ROW(lane), kaA = LDM_A_K(lane);
    const int rbB = LDM_B_ROW(lane), kbB = LDM_B_K(lane);
    const int rw = wg * 16;

    #define LOAD_KV(buf, kbase) do {                                          \
        _Pragma("unroll")                                                     \
        for (int i = 0; i < 8; i++) {                                         \
            int idx = gt + i * 128;                                           \
            int row = idx >> 4, ch = idx & 15;                                \
            cp16a(sgb + ((buf ? GOFF_K1 : GOFF_K0) + row * KLD + ch * 8) * 2, \
                  keys + (size_t)((kbase) + row) * KSZ + ch * 8);             \
        }                                                                     \
        _Pragma("unroll")                                                     \
        for (int i = 0; i < 8; i++) {                                         \
            int idx = gt + i * 128;                                           \
            int row = idx >> 3, ch = idx & 7;                                 \
            cp16a(sgb + ((buf ? GOFF_VT1 : GOFF_VT0) + row * VLD + ch * 8) * 2, \
                  valsT + (size_t)row * SEQ + (kbase) + ch * 8);              \
        }                                                                     \
    } while (0)

    // stage Q through K0 region
    #pragma unroll
    for (int i = 0; i < 8; i++) {
        int idx = gt + i * 128;
        int row = idx >> 4, ch = idx & 15;
        cp16a(sgb + (row * KLD + ch * 8) * 2,
              keys + (size_t)(qbase + row) * KSZ + ch * 8);
    }
    CP_COMMIT();
    CP_WAIT(0);
    GBAR();

    // Q fragments via ldmatrix (a-type)
    unsigned qa[8][4];
    {
        const unsigned qW = sgb + ((rw + raA) * KLD + kaA) * 2;
        #pragma unroll
        for (int ks = 0; ks < 8; ks++)
            ldmat_x4(qa[ks][0], qa[ks][1], qa[ks][2], qa[ks][3], qW + ks * 32);
    }
    GBAR();

    LOAD_KV(0, 0);
    CP_COMMIT();

    float O[16][4];
    #pragma unroll
    for (int nt = 0; nt < 16; nt++)
        #pragma unroll
        for (int i = 0; i < 4; i++) O[nt][i] = 0.f;
    float mrow[2] = {-1e30f, -1e30f};
    float lrow[2] = {0.f, 0.f};

    for (int j = 0; j < nkt; j++) {
        if (j + 1 < nkt) {
            LOAD_KV((j + 1) & 1, (j + 1) * AK);
            CP_COMMIT();
            CP_WAIT(1);
        } else {
            CP_WAIT(0);
        }
        GBAR();

        const unsigned kW = sgb + ((j & 1) ? GOFF_K1 : GOFF_K0) * 2
                          + (rbB * KLD + kbB) * 2;
        const unsigned vW = sgb + ((j & 1) ? GOFF_VT1 : GOFF_VT0) * 2
                          + (rbB * VLD + kbB) * 2;
        const int kbase = j * AK;

        // S = Q @ K^T : 16 rows x 64 keys
        float s[8][4];
        #pragma unroll
        for (int nt = 0; nt < 8; nt++)
            #pragma unroll
            for (int i = 0; i < 4; i++) s[nt][i] = 0.f;

        #pragma unroll
        for (int ks = 0; ks < 8; ks++) {
            #pragma unroll
            for (int ntp = 0; ntp < 4; ntp++) {
                unsigned b0a, b1a, b0b, b1b;
                ldmat_x4(b0a, b1a, b0b, b1b, kW + (ntp * 16 * KLD + ks * 16) * 2);
                mma_f16(s[2 * ntp],
                        qa[ks][0], qa[ks][1], qa[ks][2], qa[ks][3], b0a, b1a);
                mma_f16(s[2 * ntp + 1],
                        qa[ks][0], qa[ks][1], qa[ks][2], qa[ks][3], b0b, b1b);
            }
        }

        #pragma unroll
        for (int nt = 0; nt < 8; nt++)
            #pragma unroll
            for (int i = 0; i < 4; i++) s[nt][i] *= scale;

        // causal mask on diagonal tile only, exactly -100
        if (j == nkt - 1) {
            const int qg0 = qbase + rw + g;
            const int qg1 = qg0 + 8;
            #pragma unroll
            for (int nt = 0; nt < 8; nt++) {
                int kg = kbase + nt * 8 + 2 * t;
                if (kg     > qg0) s[nt][0] = -100.0f;
                if (kg + 1 > qg0) s[nt][1] = -100.0f;
                if (kg     > qg1) s[nt][2] = -100.0f;
                if (kg + 1 > qg1) s[nt][3] = -100.0f;
            }
        }

        // online softmax; O-rescale only when the running max changes
        #pragma unroll
        for (int h = 0; h < 2; h++) {
            float mx = -1e30f;
            #pragma unroll
            for (int nt = 0; nt < 8; nt++)
                mx = fmaxf(mx, fmaxf(s[nt][2 * h], s[nt][2 * h + 1]));
            mx = fmaxf(mx, __shfl_xor_sync(0xffffffffu, mx, 1));
            mx = fmaxf(mx, __shfl_xor_sync(0xffffffffu, mx, 2));
            if (mx > mrow[h]) {
                float alpha = __expf(mrow[h] - mx);
                mrow[h] = mx;
                lrow[h] *= alpha;
                #pragma unroll
                for (int nt = 0; nt < 16; nt++) {
                    O[nt][2 * h]     *= alpha;
                    O[nt][2 * h + 1] *= alpha;
                }
            }
            float m = mrow[h];
            float sum = 0.f;
            #pragma unroll
            for (int nt = 0; nt < 8; nt++) {
                float p0 = __expf(s[nt][2 * h] - m);
                float p1 = __expf(s[nt][2 * h + 1] - m);
                s[nt][2 * h] = p0; s[nt][2 * h + 1] = p1;
                sum += p0 + p1;
            }
            sum += __shfl_xor_sync(0xffffffffu, sum, 1);
            sum += __shfl_xor_sync(0xffffffffu, sum, 2);
            lrow[h] += sum;
        }

        // O += P @ V : P A-fragments built in registers from S accumulators.
        // A-frag (ks): a0=(row g, k 16ks+2t..+1)   = pack(s[2ks][0], s[2ks][1])
        //              a1=(row g+8, same)          = pack(s[2ks][2], s[2ks][3])
        //              a2=(row g, k 16ks+8+2t..+1) = pack(s[2ks+1][0], s[2ks+1][1])
        //              a3=(row g+8, same)          = pack(s[2ks+1][2], s[2ks+1][3])
        #pragma unroll
        for (int ks = 0; ks < 4; ks++) {
            unsigned pa0 = packh2(s[2 * ks][0], s[2 * ks][1]);
            unsigned pa1 = packh2(s[2 * ks][2], s[2 * ks][3]);
            unsigned pa2 = packh2(s[2 * ks + 1][0], s[2 * ks + 1][1]);
            unsigned pa3 = packh2(s[2 * ks + 1][2], s[2 * ks + 1][3]);
            #pragma unroll
            for (int ntp = 0; ntp < 8; ntp++) {
                unsigned b0a, b1a, b0b, b1b;
                ldmat_x4(b0a, b1a, b0b, b1b, vW + (ntp * 16 * VLD + ks * 16) * 2);
                mma_f16(O[2 * ntp], pa0, pa1, pa2, pa3, b0a, b1a);
                mma_f16(O[2 * ntp + 1], pa0, pa1, pa2, pa3, b0b, b1b);
            }
        }
        GBAR();
    }

    // epilogue: normalize, write out[:, 1024:1152]
    {
        float inv0 = 1.0f / lrow[0];
        float inv1 = 1.0f / lrow[1];
        int qg0 = qbase + rw + g;
        size_t base0 = ((size_t)bq * SEQ + qg0) * OUTD + DIMS;
        size_t base1 = base0 + (size_t)8 * OUTD;
        #pragma unroll
        for (int nt = 0; nt < 16; nt++) {
            int c = nt * 8 + 2 * t;
            *(float2*)(out + base0 + c) = make_float2(O[nt][0] * inv0, O[nt][1] * inv0);
            *(float2*)(out + base1 + c) = make_float2(O[nt][2] * inv1, O[nt][3] * inv1);
        }
    }
}

// ---------------------------------------------------------------------------
extern "C" void kernel_launch(void* const* d_in, const int* in_sizes, int n_in,
                              void* d_out, int out_size) {
    const float* X  = (const float*)d_in[0];
    const float* Wk = (const float*)d_in[1];
    const float* bk = (const float*)d_in[2];
    const float* Wv = (const float*)d_in[3];
    const float* bv = (const float*)d_in[4];
    float* out = (float*)d_out;

    prep_kernel<<<XBLKS + 64, 256>>>(X, out, Wk, Wv);

    cudaFuncSetAttribute(kv_gemm_f16, cudaFuncAttributeMaxDynamicSharedMemorySize,
                         GEMM_SMEM_BYTES);
    kv_gemm_f16<<<M_TOTAL / 128, 512, GEMM_SMEM_BYTES>>>(bk, bv);

    cudaFuncSetAttribute(attn_kernel, cudaFuncAttributeMaxDynamicSharedMemorySize,
                         ATTN_SMEM_BYTES);
    attn_kernel<<<dim3(NQT / 2, BATCH), 256, ATTN_SMEM_BYTES>>>(out);
}